// round 2
// baseline (speedup 1.0000x reference)
#include <cuda_runtime.h>

// Residual quantization, N=65536, D=128, M=8, K=256.
// v2: register-tiled distance GEMM. Block = 512 threads = (ty 0..31) x (tx 0..15).
// Block owns 128 vectors (residuals in smem); thread computes a 4-vector x
// 16-codeword tile of <res, c> with packed fma.rn.f32x2 accumulators in regs.
// Codebook XOR-swizzled in smem for 2-phase (minimum) LDS on all access patterns.

#define NV 65536
#define DD 128
#define MS 8
#define KC 256
#define TPB 512
#define VB 128                    // vectors per block
#define RPAD 132                  // residual row stride (floats), offsets bank groups
#define SMEM_FLOATS (KC * DD + VB * RPAD + KC)
#define SMEM_BYTES (SMEM_FLOATS * 4)

typedef unsigned long long u64;

__device__ __forceinline__ void upk2(u64 v, float& lo, float& hi) {
    asm("mov.b64 {%0, %1}, %2;" : "=f"(lo), "=f"(hi) : "l"(v));
}
// Packed dual-fp32 FMA (Blackwell FFMA2), PTX-only.
__device__ __forceinline__ void ffma2(u64& d, u64 a, u64 b) {
    asm("fma.rn.f32x2 %0, %1, %2, %0;" : "+l"(d) : "l"(a), "l"(b));
}

__global__ void __launch_bounds__(TPB, 1)
rq_kernel(const float* __restrict__ x, const float* __restrict__ cb,
          float* __restrict__ out_recon, float* __restrict__ out_codes,
          float* __restrict__ out_side)
{
    extern __shared__ float sm[];
    float* sC = sm;                    // [KC][DD] codebook, XOR-swizzled float4 groups
    float* sR = sm + KC * DD;          // [VB][RPAD] residuals
    float* sN = sR + VB * RPAD;        // [KC] codeword squared norms

    const int tid = threadIdx.x;
    const int tx = tid & 15;           // codeword group
    const int ty = tid >> 4;           // vector group (0..31)
    const int vbase = blockIdx.x * VB;
    const int swz = tx & 7;

    // ---- init: x tile -> residual smem (coalesced) ----
    {
        const float4* xs = (const float4*)(x + (size_t)vbase * DD);
        #pragma unroll
        for (int t = 0; t < (VB * DD / 4) / TPB; ++t) {   // 8 iters
            int i = tid + TPB * t;
            int vv = i >> 5, j = i & 31;
            *(float4*)(sR + vv * RPAD + 4 * j) = xs[i];
        }
    }

    for (int m = 0; m < MS; ++m) {
        __syncthreads();   // previous stage done reading sC / writing sR
        // ---- stage codebook into smem, swizzled: group j of row k at j^(k&7) ----
        {
            const float4* src = (const float4*)(cb + (size_t)m * KC * DD);
            #pragma unroll
            for (int t = 0; t < (KC * DD / 4) / TPB; ++t) {  // 16 iters
                int i = tid + TPB * t;
                int k = i >> 5, j = i & 31;
                *(float4*)(sC + k * DD + 4 * (j ^ (k & 7))) = src[i];
            }
        }
        __syncthreads();
        // ---- codeword squared norms (thread k < 256), swizzle-aware read ----
        if (tid < KC) {
            const float* row = sC + tid * DD;
            int c7 = tid & 7;
            float s = 0.f;
            #pragma unroll
            for (int j = 0; j < 32; ++j) {
                float4 v = *(const float4*)(row + 4 * (j ^ c7));
                s = fmaf(v.x, v.x, s); s = fmaf(v.y, v.y, s);
                s = fmaf(v.z, v.z, s); s = fmaf(v.w, v.w, s);
            }
            sN[tid] = s;
        }
        __syncthreads();

        // ---- distance GEMM: acc[v][kk] = <res[ty*4+v], c[tx+16*kk]> ----
        u64 acc[64];
        #pragma unroll
        for (int i = 0; i < 64; ++i) acc[i] = 0ull;

        #pragma unroll 4
        for (int j = 0; j < 32; ++j) {
            ulonglong2 rr[4];
            #pragma unroll
            for (int v = 0; v < 4; ++v)
                rr[v] = *(const ulonglong2*)(sR + (ty * 4 + v) * RPAD + 4 * j);
            const int joff = 16 * (j ^ swz);   // byte offset within a row
            #pragma unroll
            for (int kk = 0; kk < 16; ++kk) {
                const char* base = (const char*)(sC + (tx + 16 * kk) * DD);
                ulonglong2 cc = *(const ulonglong2*)(base + joff);
                #pragma unroll
                for (int v = 0; v < 4; ++v) {
                    ffma2(acc[kk * 4 + v], rr[v].x, cc.x);
                    ffma2(acc[kk * 4 + v], rr[v].y, cc.y);
                }
            }
        }

        // ---- per-thread argmin over its 16 codewords (sortable-bits key) ----
        u64 best[4];
        #pragma unroll
        for (int v = 0; v < 4; ++v) best[v] = ~0ull;
        #pragma unroll
        for (int kk = 0; kk < 16; ++kk) {
            int k = tx + 16 * kk;
            float cn = sN[k];
            #pragma unroll
            for (int v = 0; v < 4; ++v) {
                float a, b;
                upk2(acc[kk * 4 + v], a, b);
                float d2v = fmaf(-2.0f, a + b, cn);
                unsigned bits = __float_as_uint(d2v);
                bits ^= (bits & 0x80000000u) ? 0xFFFFFFFFu : 0x80000000u;
                u64 key = ((u64)bits << 32) | (unsigned)k;
                if (key < best[v]) best[v] = key;
            }
        }
        // ---- butterfly min across the 16-lane tx group (also warp-syncs) ----
        #pragma unroll
        for (int s = 1; s < 16; s <<= 1) {
            #pragma unroll
            for (int v = 0; v < 4; ++v) {
                u64 o = __shfl_xor_sync(0xFFFFFFFFu, best[v], s);
                if (o < best[v]) best[v] = o;
            }
        }

        // ---- epilogue: owning half-warp updates its 4 vectors ----
        #pragma unroll
        for (int v = 0; v < 4; ++v) {
            const int k = (int)(unsigned)best[v];          // low 32 bits = index
            const int vec = ty * 4 + v;
            const int gvec = vbase + vec;
            const int k7 = k & 7;
            #pragma unroll
            for (int t = 0; t < 2; ++t) {
                int j = tx + 16 * t;
                float4 c = *(const float4*)(sC + k * DD + 4 * (j ^ k7));
                float4 r = *(const float4*)(sR + vec * RPAD + 4 * j);
                r.x -= c.x; r.y -= c.y; r.z -= c.z; r.w -= c.w;
                *(float4*)(sR + vec * RPAD + 4 * j) = r;
                float4 xv = *(const float4*)(x + (size_t)gvec * DD + 4 * j);
                float4 rec = make_float4(xv.x - r.x, xv.y - r.y, xv.z - r.z, xv.w - r.w);
                *(float4*)(out_side + ((size_t)m * NV + gvec) * DD + 4 * j) = rec;
                if (m == MS - 1)
                    *(float4*)(out_recon + (size_t)gvec * DD + 4 * j) = rec;
            }
            // one-hot codes row (zero-fill folded in)
            float4* cd = (float4*)(out_codes + (size_t)gvec * (MS * KC) + (size_t)m * KC);
            const int q = k >> 2, rsel = k & 3;
            #pragma unroll
            for (int u = 0; u < 4; ++u) {
                int g = tx + 16 * u;
                float4 vv = make_float4(0.f, 0.f, 0.f, 0.f);
                if (g == q) {
                    if      (rsel == 0) vv.x = 1.f;
                    else if (rsel == 1) vv.y = 1.f;
                    else if (rsel == 2) vv.z = 1.f;
                    else                vv.w = 1.f;
                }
                cd[g] = vv;
            }
        }
    }
}

extern "C" void kernel_launch(void* const* d_in, const int* in_sizes, int n_in,
                              void* d_out, int out_size)
{
    const float* x  = (const float*)d_in[0];   // (N, D) fp32
    const float* cb = (const float*)d_in[1];   // (M, K, D) fp32

    float* out       = (float*)d_out;
    float* out_recon = out;                                // N*D
    float* out_codes = out + (size_t)NV * DD;              // N*M*K
    float* out_side  = out_codes + (size_t)NV * MS * KC;   // M*N*D

    cudaFuncSetAttribute(rq_kernel, cudaFuncAttributeMaxDynamicSharedMemorySize, SMEM_BYTES);
    rq_kernel<<<NV / VB, TPB, SMEM_BYTES>>>(x, cb, out_recon, out_codes, out_side);
}

// round 4
// speedup vs baseline: 2.6620x; 2.6620x over previous
#include <cuda_runtime.h>

// Residual quantization, N=65536, D=128, M=8, K=256.
// v3 (resubmit — round 3 was an infra failure, kernel never ran):
// register-tiled distance GEMM with the register budget fixed:
// 256 threads/block (=> 256 regs/thread budget; v2's 512 threads capped at 128
// and spilled the 128-reg accumulator tile to local memory).
// Block = (tx 0..15) x (ty 0..15), owns 64 vectors (residuals in smem).
// Thread computes a 4-vector x 16-codeword tile of <res,c> with packed
// fma.rn.f32x2 accumulators in registers. Codebook XOR-swizzled in smem.

#define NV 65536
#define DD 128
#define MS 8
#define KC 256
#define TPB 256
#define VB 64                     // vectors per block
#define RPAD 132                  // residual row stride (floats)
#define SMEM_FLOATS (KC * DD + VB * RPAD + KC)
#define SMEM_BYTES (SMEM_FLOATS * 4)

typedef unsigned long long u64;

__device__ __forceinline__ void upk2(u64 v, float& lo, float& hi) {
    asm("mov.b64 {%0, %1}, %2;" : "=f"(lo), "=f"(hi) : "l"(v));
}
// Packed dual-fp32 FMA (Blackwell FFMA2), PTX-only.
__device__ __forceinline__ void ffma2(u64& d, u64 a, u64 b) {
    asm("fma.rn.f32x2 %0, %1, %2, %0;" : "+l"(d) : "l"(a), "l"(b));
}

__global__ void __launch_bounds__(TPB, 1)
rq_kernel(const float* __restrict__ x, const float* __restrict__ cb,
          float* __restrict__ out_recon, float* __restrict__ out_codes,
          float* __restrict__ out_side)
{
    extern __shared__ float sm[];
    float* sC = sm;                    // [KC][DD] codebook, XOR-swizzled float4 groups
    float* sR = sm + KC * DD;          // [VB][RPAD] residuals
    float* sN = sR + VB * RPAD;        // [KC] codeword squared norms

    const int tid = threadIdx.x;
    const int tx = tid & 15;           // codeword group
    const int ty = tid >> 4;           // vector group (0..15)
    const int vbase = blockIdx.x * VB;
    const int swz = tx & 7;

    // ---- init: x tile -> residual smem (coalesced) ----
    {
        const float4* xs = (const float4*)(x + (size_t)vbase * DD);
        #pragma unroll
        for (int t = 0; t < (VB * DD / 4) / TPB; ++t) {   // 8 iters
            int i = tid + TPB * t;
            int vv = i >> 5, j = i & 31;
            *(float4*)(sR + vv * RPAD + 4 * j) = xs[i];
        }
    }

    for (int m = 0; m < MS; ++m) {
        __syncthreads();   // previous stage done reading sC / writing sR
        // ---- stage codebook into smem, swizzled: group j of row k at j^(k&7) ----
        {
            const float4* src = (const float4*)(cb + (size_t)m * KC * DD);
            #pragma unroll
            for (int t = 0; t < (KC * DD / 4) / TPB; ++t) {  // 32 iters
                int i = tid + TPB * t;
                int k = i >> 5, j = i & 31;
                *(float4*)(sC + k * DD + 4 * (j ^ (k & 7))) = src[i];
            }
        }
        __syncthreads();
        // ---- codeword squared norms (thread k), swizzle-aware read ----
        {
            const float* row = sC + tid * DD;
            int c7 = tid & 7;
            float s = 0.f;
            #pragma unroll
            for (int j = 0; j < 32; ++j) {
                float4 v = *(const float4*)(row + 4 * (j ^ c7));
                s = fmaf(v.x, v.x, s); s = fmaf(v.y, v.y, s);
                s = fmaf(v.z, v.z, s); s = fmaf(v.w, v.w, s);
            }
            sN[tid] = s;
        }
        __syncthreads();

        // ---- distance GEMM: acc[kk][v] = <res[ty*4+v], c[tx+16*kk]> ----
        u64 acc[64];
        #pragma unroll
        for (int i = 0; i < 64; ++i) acc[i] = 0ull;

        #pragma unroll 2
        for (int j = 0; j < 32; ++j) {
            ulonglong2 rr[4];
            #pragma unroll
            for (int v = 0; v < 4; ++v)
                rr[v] = *(const ulonglong2*)(sR + (ty * 4 + v) * RPAD + 4 * j);
            const int joff = 16 * (j ^ swz);   // byte offset within a row
            #pragma unroll
            for (int kk = 0; kk < 16; ++kk) {
                const char* base = (const char*)(sC + (tx + 16 * kk) * DD);
                ulonglong2 cc = *(const ulonglong2*)(base + joff);
                #pragma unroll
                for (int v = 0; v < 4; ++v) {
                    ffma2(acc[kk * 4 + v], rr[v].x, cc.x);
                    ffma2(acc[kk * 4 + v], rr[v].y, cc.y);
                }
            }
        }

        // ---- per-thread argmin over its 16 codewords (sortable-bits key) ----
        u64 best[4];
        #pragma unroll
        for (int v = 0; v < 4; ++v) best[v] = ~0ull;
        #pragma unroll
        for (int kk = 0; kk < 16; ++kk) {
            int k = tx + 16 * kk;
            float cn = sN[k];
            #pragma unroll
            for (int v = 0; v < 4; ++v) {
                float a, b;
                upk2(acc[kk * 4 + v], a, b);
                float d2v = fmaf(-2.0f, a + b, cn);
                unsigned bits = __float_as_uint(d2v);
                bits ^= (bits & 0x80000000u) ? 0xFFFFFFFFu : 0x80000000u;
                u64 key = ((u64)bits << 32) | (unsigned)k;
                if (key < best[v]) best[v] = key;
            }
        }
        // ---- butterfly min across the 16-lane tx group ----
        #pragma unroll
        for (int s = 1; s < 16; s <<= 1) {
            #pragma unroll
            for (int v = 0; v < 4; ++v) {
                u64 o = __shfl_xor_sync(0xFFFFFFFFu, best[v], s);
                if (o < best[v]) best[v] = o;
            }
        }

        // ---- epilogue: owning half-warp updates its 4 vectors ----
        #pragma unroll
        for (int v = 0; v < 4; ++v) {
            const int k = (int)(unsigned)best[v];          // low 32 bits = index
            const int vec = ty * 4 + v;
            const int gvec = vbase + vec;
            const int k7 = k & 7;
            #pragma unroll
            for (int t = 0; t < 2; ++t) {
                int j = tx + 16 * t;
                float4 c = *(const float4*)(sC + k * DD + 4 * (j ^ k7));
                float4 r = *(const float4*)(sR + vec * RPAD + 4 * j);
                r.x -= c.x; r.y -= c.y; r.z -= c.z; r.w -= c.w;
                *(float4*)(sR + vec * RPAD + 4 * j) = r;
                float4 xv = *(const float4*)(x + (size_t)gvec * DD + 4 * j);
                float4 rec = make_float4(xv.x - r.x, xv.y - r.y, xv.z - r.z, xv.w - r.w);
                *(float4*)(out_side + ((size_t)m * NV + gvec) * DD + 4 * j) = rec;
                if (m == MS - 1)
                    *(float4*)(out_recon + (size_t)gvec * DD + 4 * j) = rec;
            }
            // one-hot codes row (zero-fill folded in)
            float4* cd = (float4*)(out_codes + (size_t)gvec * (MS * KC) + (size_t)m * KC);
            const int q = k >> 2, rsel = k & 3;
            #pragma unroll
            for (int u = 0; u < 4; ++u) {
                int g = tx + 16 * u;
                float4 vv = make_float4(0.f, 0.f, 0.f, 0.f);
                if (g == q) {
                    if      (rsel == 0) vv.x = 1.f;
                    else if (rsel == 1) vv.y = 1.f;
                    else if (rsel == 2) vv.z = 1.f;
                    else                vv.w = 1.f;
                }
                cd[g] = vv;
            }
        }
    }
}

extern "C" void kernel_launch(void* const* d_in, const int* in_sizes, int n_in,
                              void* d_out, int out_size)
{
    const float* x  = (const float*)d_in[0];   // (N, D) fp32
    const float* cb = (const float*)d_in[1];   // (M, K, D) fp32

    float* out       = (float*)d_out;
    float* out_recon = out;                                // N*D
    float* out_codes = out + (size_t)NV * DD;              // N*M*K
    float* out_side  = out_codes + (size_t)NV * MS * KC;   // M*N*D

    cudaFuncSetAttribute(rq_kernel, cudaFuncAttributeMaxDynamicSharedMemorySize, SMEM_BYTES);
    rq_kernel<<<NV / VB, TPB, SMEM_BYTES>>>(x, cb, out_recon, out_codes, out_side);
}

// round 6
// speedup vs baseline: 2.9703x; 1.1158x over previous
#include <cuda_runtime.h>

// Residual quantization, N=65536, D=128, M=8, K=256.
// v4: v3's register-tiled FFMA2 GEMM (measured at 100% FMA rate) + overhead kill:
//  - codebook staged in two 64KB half-buffers, cp.async-prefetched 2 segments
//    ahead (fully hidden under GEMM compute)
//  - codeword norms precomputed once by a tiny kernel (were recomputed 8192x)
//  - epilogue reads the winning codeword row from global (L2-hot), freeing
//    smem buffers for the prefetch pipeline.

#define NV 65536
#define DD 128
#define MS 8
#define KC 256
#define TPB 256
#define VB 64                     // vectors per block
#define RPAD 132                  // residual row stride (floats)
#define HROWS 128                 // codewords per half-segment
#define HFLOATS (HROWS * DD)      // 16384 floats = 64KB per half buffer
#define SMEM_FLOATS (2 * HFLOATS + VB * RPAD + MS * KC)
#define SMEM_BYTES (SMEM_FLOATS * 4)

typedef unsigned long long u64;

__device__ float g_norms[MS * KC];

__device__ __forceinline__ void upk2(u64 v, float& lo, float& hi) {
    asm("mov.b64 {%0, %1}, %2;" : "=f"(lo), "=f"(hi) : "l"(v));
}
// Packed dual-fp32 FMA (Blackwell FFMA2), PTX-only.
__device__ __forceinline__ void ffma2(u64& d, u64 a, u64 b) {
    asm("fma.rn.f32x2 %0, %1, %2, %0;" : "+l"(d) : "l"(a), "l"(b));
}
__device__ __forceinline__ void cp16(float* dst_smem, const float* src_gmem) {
    unsigned s = (unsigned)__cvta_generic_to_shared(dst_smem);
    asm volatile("cp.async.cg.shared.global [%0], [%1], 16;" :: "r"(s), "l"(src_gmem));
}
__device__ __forceinline__ void cp_commit() {
    asm volatile("cp.async.commit_group;");
}

// ---- norms: one thread per (stage, codeword) ----
__global__ void norms_kernel(const float* __restrict__ cb) {
    int m = blockIdx.x, k = threadIdx.x;
    const float4* row = (const float4*)(cb + ((size_t)m * KC + k) * DD);
    float s = 0.f;
    #pragma unroll
    for (int j = 0; j < 32; ++j) {
        float4 v = row[j];
        s = fmaf(v.x, v.x, s); s = fmaf(v.y, v.y, s);
        s = fmaf(v.z, v.z, s); s = fmaf(v.w, v.w, s);
    }
    g_norms[m * KC + k] = s;
}

// Prefetch half-segment (stage ms, half h) into buf (swizzled), 16B x 16 per thread.
__device__ __forceinline__ void prefetch_half(float* buf, const float* __restrict__ cb,
                                              int ms, int h, int tid) {
    const float* src = cb + ((size_t)ms * KC + h * HROWS) * DD;
    #pragma unroll
    for (int t = 0; t < 16; ++t) {
        int i = tid + TPB * t;          // 0..4095 16B-chunks
        int r = i >> 5, jj = i & 31;
        cp16(buf + r * DD + 4 * (jj ^ (r & 7)), src + 4 * i);
    }
    cp_commit();
}

__global__ void __launch_bounds__(TPB, 1)
rq_kernel(const float* __restrict__ x, const float* __restrict__ cb,
          float* __restrict__ out_recon, float* __restrict__ out_codes,
          float* __restrict__ out_side)
{
    extern __shared__ float sm[];
    float* sB0 = sm;                       // half buffer 0 (swizzled)
    float* sB1 = sm + HFLOATS;             // half buffer 1 (swizzled)
    float* sR  = sm + 2 * HFLOATS;         // [VB][RPAD] residuals
    float* sN  = sR + VB * RPAD;           // [MS*KC] norms (all stages)

    const int tid = threadIdx.x;
    const int tx = tid & 15;               // codeword group
    const int ty = tid >> 4;               // vector group (0..15)
    const int vbase = blockIdx.x * VB;
    const int swz = tx & 7;

    // Kick off prefetch of segments 0 and 1 immediately.
    prefetch_half(sB0, cb, 0, 0, tid);
    prefetch_half(sB1, cb, 0, 1, tid);

    // ---- init: x tile -> residual smem; norms -> smem ----
    {
        const float4* xs = (const float4*)(x + (size_t)vbase * DD);
        #pragma unroll
        for (int t = 0; t < (VB * DD / 4) / TPB; ++t) {   // 8 iters
            int i = tid + TPB * t;
            int vv = i >> 5, j = i & 31;
            *(float4*)(sR + vv * RPAD + 4 * j) = xs[i];
        }
        #pragma unroll
        for (int t = 0; t < (MS * KC) / TPB; ++t)
            sN[tid + TPB * t] = g_norms[tid + TPB * t];
    }

    for (int m = 0; m < MS; ++m) {
        u64 best[4];
        #pragma unroll
        for (int v = 0; v < 4; ++v) best[v] = ~0ull;

        #pragma unroll
        for (int h = 0; h < 2; ++h) {
            // wait for this segment's cp.async group; last segment needs full drain
            if (m == 7 && h == 1) asm volatile("cp.async.wait_group 0;");
            else                  asm volatile("cp.async.wait_group 1;");
            __syncthreads();   // buffer data visible; also: prev writes to sR visible

            float* sC = h ? sB1 : sB0;

            // ---- distance GEMM over this half's 128 codewords ----
            u64 acc[32];
            #pragma unroll
            for (int i = 0; i < 32; ++i) acc[i] = 0ull;

            #pragma unroll 2
            for (int j = 0; j < 32; ++j) {
                ulonglong2 rr[4];
                #pragma unroll
                for (int v = 0; v < 4; ++v)
                    rr[v] = *(const ulonglong2*)(sR + (ty * 4 + v) * RPAD + 4 * j);
                const int joff = 16 * (j ^ swz);   // byte offset within a row
                #pragma unroll
                for (int kk = 0; kk < 8; ++kk) {
                    const char* base = (const char*)(sC + (tx + 16 * kk) * DD);
                    ulonglong2 cc = *(const ulonglong2*)(base + joff);
                    #pragma unroll
                    for (int v = 0; v < 4; ++v) {
                        ffma2(acc[kk * 4 + v], rr[v].x, cc.x);
                        ffma2(acc[kk * 4 + v], rr[v].y, cc.y);
                    }
                }
            }

            // ---- fold this half into per-thread argmin (sortable-bits key) ----
            #pragma unroll
            for (int kk = 0; kk < 8; ++kk) {
                int k = h * HROWS + tx + 16 * kk;
                float cn = sN[m * KC + k];
                #pragma unroll
                for (int v = 0; v < 4; ++v) {
                    float a, b;
                    upk2(acc[kk * 4 + v], a, b);
                    float d2v = fmaf(-2.0f, a + b, cn);
                    unsigned bits = __float_as_uint(d2v);
                    bits ^= (bits & 0x80000000u) ? 0xFFFFFFFFu : 0x80000000u;
                    u64 key = ((u64)bits << 32) | (unsigned)k;
                    if (key < best[v]) best[v] = key;
                }
            }

            __syncthreads();   // all warps done reading sC -> safe to overwrite
            if (m < 7) prefetch_half(sC, cb, m + 1, h, tid);
        }

        // ---- butterfly min across the 16-lane tx group ----
        #pragma unroll
        for (int s = 1; s < 16; s <<= 1) {
            #pragma unroll
            for (int v = 0; v < 4; ++v) {
                u64 o = __shfl_xor_sync(0xFFFFFFFFu, best[v], s);
                if (o < best[v]) best[v] = o;
            }
        }

        // ---- epilogue: winner row read from global cb (L2-hot) ----
        #pragma unroll
        for (int v = 0; v < 4; ++v) {
            const int k = (int)(unsigned)best[v];          // low 32 bits = index
            const int vec = ty * 4 + v;
            const int gvec = vbase + vec;
            const float4* crow = (const float4*)(cb + ((size_t)m * KC + k) * DD);
            #pragma unroll
            for (int t = 0; t < 2; ++t) {
                int j = tx + 16 * t;
                float4 c = __ldg(crow + j);
                float4 r = *(const float4*)(sR + vec * RPAD + 4 * j);
                r.x -= c.x; r.y -= c.y; r.z -= c.z; r.w -= c.w;
                *(float4*)(sR + vec * RPAD + 4 * j) = r;
                float4 xv = *(const float4*)(x + (size_t)gvec * DD + 4 * j);
                float4 rec = make_float4(xv.x - r.x, xv.y - r.y, xv.z - r.z, xv.w - r.w);
                *(float4*)(out_side + ((size_t)m * NV + gvec) * DD + 4 * j) = rec;
                if (m == MS - 1)
                    *(float4*)(out_recon + (size_t)gvec * DD + 4 * j) = rec;
            }
            // one-hot codes row (zero-fill folded in)
            float4* cd = (float4*)(out_codes + (size_t)gvec * (MS * KC) + (size_t)m * KC);
            const int q = k >> 2, rsel = k & 3;
            #pragma unroll
            for (int u = 0; u < 4; ++u) {
                int g = tx + 16 * u;
                float4 vv = make_float4(0.f, 0.f, 0.f, 0.f);
                if (g == q) {
                    if      (rsel == 0) vv.x = 1.f;
                    else if (rsel == 1) vv.y = 1.f;
                    else if (rsel == 2) vv.z = 1.f;
                    else                vv.w = 1.f;
                }
                cd[g] = vv;
            }
        }
        // NOTE: sR writes above are read next stage only by the same 16-thread
        // group that wrote them; the __syncthreads at the next segment's top
        // provides the block-wide ordering anyway.
    }
}

extern "C" void kernel_launch(void* const* d_in, const int* in_sizes, int n_in,
                              void* d_out, int out_size)
{
    const float* x  = (const float*)d_in[0];   // (N, D) fp32
    const float* cb = (const float*)d_in[1];   // (M, K, D) fp32

    float* out       = (float*)d_out;
    float* out_recon = out;                                // N*D
    float* out_codes = out + (size_t)NV * DD;              // N*M*K
    float* out_side  = out_codes + (size_t)NV * MS * KC;   // M*N*D

    norms_kernel<<<MS, KC>>>(cb);
    cudaFuncSetAttribute(rq_kernel, cudaFuncAttributeMaxDynamicSharedMemorySize, SMEM_BYTES);
    rq_kernel<<<NV / VB, TPB, SMEM_BYTES>>>(x, cb, out_recon, out_codes, out_side);
}

// round 7
// speedup vs baseline: 3.0834x; 1.0381x over previous
#include <cuda_runtime.h>

// Residual quantization, N=65536, D=128, M=8, K=256.
// v5: same register-tiled FFMA2 distance GEMM, now at 2 CTAs/SM so one CTA's
// GEMM hides the other's barriers/argmin/epilogue latency (v4 ran occ=12.5%,
// fma=53.6% with a ~430us exposed serial tail).
//  - 256 threads, __launch_bounds__(256,2) => 128-reg budget
//  - segment = 64 codewords (32KB), acc tile = 16 u64 = 32 regs (no spill)
//  - 32 linear segments, cp.async ping-pong, depth-2 prefetch
//  - norms precomputed once; epilogue winner row from global cb (L2-hot)

#define NV 65536
#define DD 128
#define MS 8
#define KC 256
#define TPB 256
#define VB 64                     // vectors per block
#define RPAD 132                  // residual row stride (floats)
#define SROWS 64                  // codewords per segment
#define SFLOATS (SROWS * DD)      // 8192 floats = 32KB per buffer
#define NSEG (MS * KC / SROWS)    // 32 linear segments
#define SMEM_FLOATS (2 * SFLOATS + VB * RPAD + MS * KC)
#define SMEM_BYTES (SMEM_FLOATS * 4)

typedef unsigned long long u64;

__device__ float g_norms[MS * KC];

__device__ __forceinline__ void upk2(u64 v, float& lo, float& hi) {
    asm("mov.b64 {%0, %1}, %2;" : "=f"(lo), "=f"(hi) : "l"(v));
}
// Packed dual-fp32 FMA (Blackwell FFMA2), PTX-only.
__device__ __forceinline__ void ffma2(u64& d, u64 a, u64 b) {
    asm("fma.rn.f32x2 %0, %1, %2, %0;" : "+l"(d) : "l"(a), "l"(b));
}
__device__ __forceinline__ void cp16(float* dst_smem, const float* src_gmem) {
    unsigned s = (unsigned)__cvta_generic_to_shared(dst_smem);
    asm volatile("cp.async.cg.shared.global [%0], [%1], 16;" :: "r"(s), "l"(src_gmem));
}

// ---- norms: one thread per (stage, codeword) ----
__global__ void norms_kernel(const float* __restrict__ cb) {
    int m = blockIdx.x, k = threadIdx.x;
    const float4* row = (const float4*)(cb + ((size_t)m * KC + k) * DD);
    float s = 0.f;
    #pragma unroll
    for (int j = 0; j < 32; ++j) {
        float4 v = row[j];
        s = fmaf(v.x, v.x, s); s = fmaf(v.y, v.y, s);
        s = fmaf(v.z, v.z, s); s = fmaf(v.w, v.w, s);
    }
    g_norms[m * KC + k] = s;
}

// Prefetch linear segment seg (64 contiguous codebook rows) into buf, swizzled.
__device__ __forceinline__ void prefetch_seg(float* buf, const float* __restrict__ cb,
                                             int seg, int tid) {
    const float* src = cb + (size_t)seg * SFLOATS;
    #pragma unroll
    for (int t = 0; t < (SFLOATS / 4) / TPB; ++t) {     // 8 iters
        int i = tid + TPB * t;                          // 16B chunk id
        int r = i >> 5, jj = i & 31;
        cp16(buf + r * DD + 4 * (jj ^ (r & 7)), src + 4 * i);
    }
    asm volatile("cp.async.commit_group;");
}

__global__ void __launch_bounds__(TPB, 2)
rq_kernel(const float* __restrict__ x, const float* __restrict__ cb,
          float* __restrict__ out_recon, float* __restrict__ out_codes,
          float* __restrict__ out_side)
{
    extern __shared__ float sm[];
    float* sB[2] = { sm, sm + SFLOATS };   // ping-pong segment buffers (swizzled)
    float* sR = sm + 2 * SFLOATS;          // [VB][RPAD] residuals
    float* sN = sR + VB * RPAD;            // [MS*KC] norms

    const int tid = threadIdx.x;
    const int tx = tid & 15;               // codeword group
    const int ty = tid >> 4;               // vector group (0..15)
    const int vbase = blockIdx.x * VB;
    const int swz = tx & 7;

    // Kick off prefetch of segments 0 and 1 immediately.
    prefetch_seg(sB[0], cb, 0, tid);
    prefetch_seg(sB[1], cb, 1, tid);

    // ---- init: x tile -> residual smem; norms -> smem ----
    {
        const float4* xs = (const float4*)(x + (size_t)vbase * DD);
        #pragma unroll
        for (int t = 0; t < (VB * DD / 4) / TPB; ++t) {   // 8 iters
            int i = tid + TPB * t;
            int vv = i >> 5, j = i & 31;
            *(float4*)(sR + vv * RPAD + 4 * j) = xs[i];
        }
        #pragma unroll
        for (int t = 0; t < (MS * KC) / TPB; ++t)
            sN[tid + TPB * t] = g_norms[tid + TPB * t];
    }

    for (int m = 0; m < MS; ++m) {
        u64 best[4];
        #pragma unroll
        for (int v = 0; v < 4; ++v) best[v] = ~0ull;

        #pragma unroll
        for (int h = 0; h < 4; ++h) {
            const int seg = m * 4 + h;
            // Drain this segment's cp.async group (leaves only seg+1 pending).
            if (seg == NSEG - 1) asm volatile("cp.async.wait_group 0;");
            else                 asm volatile("cp.async.wait_group 1;");
            __syncthreads();   // buffer visible; also orders prev epilogue sR writes

            const float* sC = sB[seg & 1];

            // ---- distance GEMM over this segment's 64 codewords ----
            u64 acc[16];
            #pragma unroll
            for (int i = 0; i < 16; ++i) acc[i] = 0ull;

            #pragma unroll 2
            for (int j = 0; j < 32; ++j) {
                ulonglong2 rr[4];
                #pragma unroll
                for (int v = 0; v < 4; ++v)
                    rr[v] = *(const ulonglong2*)(sR + (ty * 4 + v) * RPAD + 4 * j);
                const int joff = 16 * (j ^ swz);   // byte offset within a row
                #pragma unroll
                for (int kk = 0; kk < 4; ++kk) {
                    const char* base = (const char*)(sC + (tx + 16 * kk) * DD);
                    ulonglong2 cc = *(const ulonglong2*)(base + joff);
                    #pragma unroll
                    for (int v = 0; v < 4; ++v) {
                        ffma2(acc[kk * 4 + v], rr[v].x, cc.x);
                        ffma2(acc[kk * 4 + v], rr[v].y, cc.y);
                    }
                }
            }

            // ---- fold into per-thread argmin (sortable-bits key) ----
            #pragma unroll
            for (int kk = 0; kk < 4; ++kk) {
                int k = h * SROWS + tx + 16 * kk;
                float cn = sN[m * KC + k];
                #pragma unroll
                for (int v = 0; v < 4; ++v) {
                    float a, b;
                    upk2(acc[kk * 4 + v], a, b);
                    float d2v = fmaf(-2.0f, a + b, cn);
                    unsigned bits = __float_as_uint(d2v);
                    bits ^= (bits & 0x80000000u) ? 0xFFFFFFFFu : 0x80000000u;
                    u64 key = ((u64)bits << 32) | (unsigned)k;
                    if (key < best[v]) best[v] = key;
                }
            }

            __syncthreads();   // all warps done reading sC -> safe to overwrite
            if (seg + 2 < NSEG) prefetch_seg(sB[seg & 1], cb, seg + 2, tid);
        }

        // ---- butterfly min across the 16-lane tx group ----
        #pragma unroll
        for (int s = 1; s < 16; s <<= 1) {
            #pragma unroll
            for (int v = 0; v < 4; ++v) {
                u64 o = __shfl_xor_sync(0xFFFFFFFFu, best[v], s);
                if (o < best[v]) best[v] = o;
            }
        }

        // ---- epilogue: winner row read from global cb (L2-hot) ----
        #pragma unroll
        for (int v = 0; v < 4; ++v) {
            const int k = (int)(unsigned)best[v];          // low 32 bits = index
            const int vec = ty * 4 + v;
            const int gvec = vbase + vec;
            const float4* crow = (const float4*)(cb + ((size_t)m * KC + k) * DD);
            #pragma unroll
            for (int t = 0; t < 2; ++t) {
                int j = tx + 16 * t;
                float4 c = __ldg(crow + j);
                float4 r = *(const float4*)(sR + vec * RPAD + 4 * j);
                r.x -= c.x; r.y -= c.y; r.z -= c.z; r.w -= c.w;
                *(float4*)(sR + vec * RPAD + 4 * j) = r;
                float4 xv = *(const float4*)(x + (size_t)gvec * DD + 4 * j);
                float4 rec = make_float4(xv.x - r.x, xv.y - r.y, xv.z - r.z, xv.w - r.w);
                *(float4*)(out_side + ((size_t)m * NV + gvec) * DD + 4 * j) = rec;
                if (m == MS - 1)
                    *(float4*)(out_recon + (size_t)gvec * DD + 4 * j) = rec;
            }
            // one-hot codes row (zero-fill folded in)
            float4* cd = (float4*)(out_codes + (size_t)gvec * (MS * KC) + (size_t)m * KC);
            const int q = k >> 2, rsel = k & 3;
            #pragma unroll
            for (int u = 0; u < 4; ++u) {
                int g = tx + 16 * u;
                float4 vv = make_float4(0.f, 0.f, 0.f, 0.f);
                if (g == q) {
                    if      (rsel == 0) vv.x = 1.f;
                    else if (rsel == 1) vv.y = 1.f;
                    else if (rsel == 2) vv.z = 1.f;
                    else                vv.w = 1.f;
                }
                cd[g] = vv;
            }
        }
    }
}

extern "C" void kernel_launch(void* const* d_in, const int* in_sizes, int n_in,
                              void* d_out, int out_size)
{
    const float* x  = (const float*)d_in[0];   // (N, D) fp32
    const float* cb = (const float*)d_in[1];   // (M, K, D) fp32

    float* out       = (float*)d_out;
    float* out_recon = out;                                // N*D
    float* out_codes = out + (size_t)NV * DD;              // N*M*K
    float* out_side  = out_codes + (size_t)NV * MS * KC;   // M*N*D

    norms_kernel<<<MS, KC>>>(cb);
    cudaFuncSetAttribute(rq_kernel, cudaFuncAttributeMaxDynamicSharedMemorySize, SMEM_BYTES);
    rq_kernel<<<NV / VB, TPB, SMEM_BYTES>>>(x, cb, out_recon, out_codes, out_side);
}